// round 6
// baseline (speedup 1.0000x reference)
#include <cuda_runtime.h>
#include <cuda_fp16.h>

// Problem constants (fixed by the reference generator)
#define NN   10000          // nodes
#define BB   2              // batch
#define FF   128            // F_IN
#define DD   128            // D_EMB
#define EPN  33             // edges per node (DEG+1), contiguous per src node
#define ROWS (BB * NN)      // 20000 rows of X / h

// GEMM tiling: 160 rows/block -> exactly 125 blocks (single wave on 148 SMs)
#define GBM    160
#define GTPB   512
#define GNBLK  (ROWS / GBM)          // 125
#define XPITCH 136                   // halves per smem row (bank-staggered)
#define XS_BYTES  (GBM * XPITCH * 2)            // 43520
#define GEMM_SMEM (XS_BYTES + 2 * 8 * GBM * 4)  // + sd partials = 53760

// Scratch (device globals — no cudaMalloc allowed)
// Interleaved h: g_hx[node*32 + grp] = {b0 h2(4g,4g+1), b0 h2(4g+2,4g+3),
//                                       b1 h2(4g,4g+1), b1 h2(4g+2,4g+3)}
__device__ uint4 g_hx[NN * 32];     // 5.12 MB, both batches interleaved
__device__ float g_s[ROWS];         // h @ a_src (fp32)
__device__ float g_d[ROWS];         // h @ a_dst (fp32)

__device__ __forceinline__ unsigned packh2(float lo, float hi) {
    __half2 h = __floats2half2_rn(lo, hi);
    return *(unsigned*)&h;
}
__device__ __forceinline__ void ffma2(unsigned long long& acc,
                                      unsigned long long a,
                                      unsigned long long b) {
    asm("fma.rn.f32x2 %0, %1, %2, %0;" : "+l"(acc) : "l"(a), "l"(b));
}
__device__ __forceinline__ unsigned long long packf2(float lo, float hi) {
    unsigned long long v;
    asm("mov.b64 %0, {%1, %2};" : "=l"(v) : "f"(lo), "f"(hi));
    return v;
}
__device__ __forceinline__ float2 unpackf2(unsigned long long v) {
    float2 r;
    asm("mov.b64 {%0, %1}, %2;" : "=f"(r.x), "=f"(r.y) : "l"(v));
    return r;
}

extern __shared__ char smem_raw[];

// ---------------------------------------------------------------------------
// Kernel A: h = X @ W via mma.sync.m16n8k16 (fp16 in, fp32 acc).
// 512 threads = 16 warps: warp = (c8 = w&7 -> cols [c8*16, c8*16+16),
//                                 mh = w>>3 -> m-tiles [mh*5, mh*5+5)).
// Each warp runs only 5 m-tiles -> half the dependent-MMA critical path,
// 4 warps per SMSP for latency hiding. W fragments register-resident.
// ---------------------------------------------------------------------------
__global__ __launch_bounds__(GTPB)
void gemm_sd_kernel(const float* __restrict__ inputs,
                    const float* __restrict__ W,
                    const float* __restrict__ W_attn) {
    __half (*Xs)[XPITCH] = (__half(*)[XPITCH])smem_raw;
    float* sd_s = (float*)(smem_raw + XS_BYTES);   // [8][GBM]
    float* sd_d = sd_s + 8 * GBM;

    const int t    = threadIdx.x;
    const int lane = t & 31;
    const int w    = t >> 5;
    const int c8   = w & 7;
    const int mh   = w >> 3;
    const int rb   = blockIdx.x * GBM;
    const int g    = lane >> 2;      // 0..7
    const int tg   = lane & 3;       // 0..3
    const int wcol = c8 * 16;

    // --- Stage X tile: fp32 global -> fp16 smem (coalesced) ---
#pragma unroll
    for (int i = 0; i < 10; ++i) {
        int idx = t + i * GTPB;
        int row = idx >> 5, c4 = idx & 31;
        float4 v = ((const float4*)inputs)[(rb + row) * 32 + c4];
        *(uint2*)&Xs[row][c4 * 4] =
            make_uint2(packh2(v.x, v.y), packh2(v.z, v.w));
    }

    // --- W fragments (col-major B frag for m16n8k16), register-resident ---
    unsigned bf[2][8][2];
#pragma unroll
    for (int nt = 0; nt < 2; ++nt) {
        const int c = wcol + nt * 8 + g;
#pragma unroll
        for (int kt = 0; kt < 8; ++kt) {
            const int k0 = kt * 16 + tg * 2;
            bf[nt][kt][0] = packh2(W[k0 * DD + c],       W[(k0 + 1) * DD + c]);
            bf[nt][kt][1] = packh2(W[(k0 + 8) * DD + c], W[(k0 + 9) * DD + c]);
        }
    }
    float as[2][2], ad[2][2];
#pragma unroll
    for (int nt = 0; nt < 2; ++nt) {
        const int c = wcol + nt * 8 + tg * 2;
        as[nt][0] = W_attn[c];       as[nt][1] = W_attn[c + 1];
        ad[nt][0] = W_attn[DD + c];  ad[nt][1] = W_attn[DD + c + 1];
    }
    __syncthreads();

    // --- Main loop: this warp's 5 m-tiles ---
#pragma unroll 1
    for (int mt = mh * 5; mt < mh * 5 + 5; ++mt) {
        float acc[2][4];
#pragma unroll
        for (int nt = 0; nt < 2; ++nt)
#pragma unroll
            for (int i = 0; i < 4; ++i) acc[nt][i] = 0.0f;

#pragma unroll
        for (int kt = 0; kt < 8; ++kt) {
            const int r0 = mt * 16 + g;
            const int c0 = kt * 16 + tg * 2;
            unsigned a0 = *(const unsigned*)&Xs[r0][c0];
            unsigned a1 = *(const unsigned*)&Xs[r0 + 8][c0];
            unsigned a2 = *(const unsigned*)&Xs[r0][c0 + 8];
            unsigned a3 = *(const unsigned*)&Xs[r0 + 8][c0 + 8];
#pragma unroll
            for (int nt = 0; nt < 2; ++nt) {
                asm volatile(
                    "mma.sync.aligned.m16n8k16.row.col.f32.f16.f16.f32 "
                    "{%0,%1,%2,%3}, {%4,%5,%6,%7}, {%8,%9}, {%0,%1,%2,%3};"
                    : "+f"(acc[nt][0]), "+f"(acc[nt][1]),
                      "+f"(acc[nt][2]), "+f"(acc[nt][3])
                    : "r"(a0), "r"(a1), "r"(a2), "r"(a3),
                      "r"(bf[nt][kt][0]), "r"(bf[nt][kt][1]));
            }
        }

        // --- Epilogue: interleaved fp16 h store + s/d partials ---
        const int row0 = rb + mt * 16 + g;      // and row0 + 8; all < ROWS
#pragma unroll
        for (int nt = 0; nt < 2; ++nt) {
            const int colbase = wcol + nt * 8 + tg * 2;
            const int grp  = colbase >> 2;
            const int slot = (colbase >> 1) & 1;
            unsigned p0 = packh2(acc[nt][0], acc[nt][1]);   // row0
            unsigned p1 = packh2(acc[nt][2], acc[nt][3]);   // row0+8
            {
                int b = row0 >= NN, node = row0 - b * NN;
                ((unsigned*)g_hx)[(node * 32 + grp) * 4 + b * 2 + slot] = p0;
            }
            {
                int r1 = row0 + 8;
                int b = r1 >= NN, node = r1 - b * NN;
                ((unsigned*)g_hx)[(node * 32 + grp) * 4 + b * 2 + slot] = p1;
            }
        }

        float ps0 = 0.f, pd0 = 0.f, ps1 = 0.f, pd1 = 0.f;
#pragma unroll
        for (int nt = 0; nt < 2; ++nt) {
            ps0 = fmaf(acc[nt][0], as[nt][0], fmaf(acc[nt][1], as[nt][1], ps0));
            pd0 = fmaf(acc[nt][0], ad[nt][0], fmaf(acc[nt][1], ad[nt][1], pd0));
            ps1 = fmaf(acc[nt][2], as[nt][0], fmaf(acc[nt][3], as[nt][1], ps1));
            pd1 = fmaf(acc[nt][2], ad[nt][0], fmaf(acc[nt][3], ad[nt][1], pd1));
        }
#pragma unroll
        for (int off = 1; off <= 2; off <<= 1) {
            ps0 += __shfl_xor_sync(0xFFFFFFFFu, ps0, off);
            pd0 += __shfl_xor_sync(0xFFFFFFFFu, pd0, off);
            ps1 += __shfl_xor_sync(0xFFFFFFFFu, ps1, off);
            pd1 += __shfl_xor_sync(0xFFFFFFFFu, pd1, off);
        }
        if (tg == 0) {   // each (c8, row) written by exactly one warp
            sd_s[c8 * GBM + mt * 16 + g]     = ps0;
            sd_d[c8 * GBM + mt * 16 + g]     = pd0;
            sd_s[c8 * GBM + mt * 16 + g + 8] = ps1;
            sd_d[c8 * GBM + mt * 16 + g + 8] = pd1;
        }
    }
    __syncthreads();

    if (t < GBM) {
        float s = 0.f, d = 0.f;
#pragma unroll
        for (int i = 0; i < 8; ++i) {
            s += sd_s[i * GBM + t];
            d += sd_d[i * GBM + t];
        }
        g_s[rb + t] = s;
        g_d[rb + t] = d;
    }
}

// ---------------------------------------------------------------------------
// Kernel B: warp-per-node attention + aggregation.
// __launch_bounds__(256, 8) clamps regs to 32 so all 8 blocks (2048 threads)
// are resident per SM (was 34 regs -> 7 blocks, occ 60%).
// ---------------------------------------------------------------------------
__global__ __launch_bounds__(256, 8)
void gat_agg_kernel(const int* __restrict__ edges,
                    float* __restrict__ out) {
    __shared__ int    offs[8][EPN];
    __shared__ float4 wpr[8][EPN];

    const int t    = threadIdx.x;
    const int lane = t & 31;
    const int wi   = t >> 5;
    const int n    = blockIdx.x * 8 + wi;

    // --- Phase 1: scores ---
    const int2 e2  = __ldg(&((const int2*)edges)[n * EPN + lane]);
    const int dstv = e2.y;
    const float s0 = __ldg(&g_s[n]);
    const float s1 = __ldg(&g_s[NN + n]);

    float sc0 = s0 + __ldg(&g_d[dstv]);
    float sc1 = s1 + __ldg(&g_d[NN + dstv]);
    sc0 = (sc0 > 0.0f) ? sc0 : 0.2f * sc0;   // leaky_relu(0.2)
    sc1 = (sc1 > 0.0f) ? sc1 : 0.2f * sc1;
    const float w0v = expf(fminf(fmaxf(sc0, -2.0f), 2.0f));
    const float w1v = expf(fminf(fmaxf(sc1, -2.0f), 2.0f));

    // edge 32 (broadcast; computed redundantly by all lanes)
    const int d32 = __ldg(&edges[(n * EPN + 32) * 2 + 1]);
    float sx0 = s0 + __ldg(&g_d[d32]);
    float sx1 = s1 + __ldg(&g_d[NN + d32]);
    sx0 = (sx0 > 0.0f) ? sx0 : 0.2f * sx0;
    sx1 = (sx1 > 0.0f) ? sx1 : 0.2f * sx1;
    const float w032 = expf(fminf(fmaxf(sx0, -2.0f), 2.0f));
    const float w132 = expf(fminf(fmaxf(sx1, -2.0f), 2.0f));

    // denom over batch-0 scores (33 edges); fold 1/denom into weights
    float dn = w0v;
#pragma unroll
    for (int off = 16; off > 0; off >>= 1)
        dn += __shfl_xor_sync(0xFFFFFFFFu, dn, off);
    dn += w032;
    const float inv = 1.0f / dn;

    offs[wi][lane] = dstv * (int)sizeof(uint4) * 32;   // byte offset of h row
    {
        const float a = w0v * inv, b = w1v * inv;
        wpr[wi][lane] = make_float4(a, a, b, b);
    }
    if (lane == 0) {
        offs[wi][32] = d32 * (int)sizeof(uint4) * 32;
        const float a = w032 * inv, b = w132 * inv;
        wpr[wi][32] = make_float4(a, a, b, b);
    }
    __syncwarp();

    // --- Phase 2: gather, 4-edge batches ---
    const char* hbase = (const char*)g_hx + lane * 16;
    unsigned long long accA = 0ull, accB = 0ull;   // feats (0,1), (2,3)

#pragma unroll
    for (int eb = 0; eb < 32; eb += 4) {
        int    of[4];
        uint4  v[4];
        float4 wp[4];
#pragma unroll
        for (int k = 0; k < 4; ++k) of[k] = offs[wi][eb + k];
#pragma unroll
        for (int k = 0; k < 4; ++k) v[k] = *(const uint4*)(hbase + of[k]);
#pragma unroll
        for (int k = 0; k < 4; ++k) wp[k] = wpr[wi][eb + k];
#pragma unroll
        for (int k = 0; k < 4; ++k) {
            const unsigned long long c0p = packf2(wp[k].x, wp[k].y);
            const unsigned long long c1p = packf2(wp[k].z, wp[k].w);
            float2 f0a = __half22float2(*(__half2*)&v[k].x);
            float2 f0b = __half22float2(*(__half2*)&v[k].y);
            float2 f1a = __half22float2(*(__half2*)&v[k].z);
            float2 f1b = __half22float2(*(__half2*)&v[k].w);
            ffma2(accA, packf2(f0a.x, f0a.y), c0p);
            ffma2(accA, packf2(f1a.x, f1a.y), c1p);
            ffma2(accB, packf2(f0b.x, f0b.y), c0p);
            ffma2(accB, packf2(f1b.x, f1b.y), c1p);
        }
    }
    {   // edge 32
        const int of = offs[wi][32];
        const float4 wp = wpr[wi][32];
        const uint4 v = *(const uint4*)(hbase + of);
        const unsigned long long c0p = packf2(wp.x, wp.y);
        const unsigned long long c1p = packf2(wp.z, wp.w);
        float2 f0a = __half22float2(*(__half2*)&v.x);
        float2 f0b = __half22float2(*(__half2*)&v.y);
        float2 f1a = __half22float2(*(__half2*)&v.z);
        float2 f1b = __half22float2(*(__half2*)&v.w);
        ffma2(accA, packf2(f0a.x, f0a.y), c0p);
        ffma2(accA, packf2(f1a.x, f1a.y), c1p);
        ffma2(accB, packf2(f0b.x, f0b.y), c0p);
        ffma2(accB, packf2(f1b.x, f1b.y), c1p);
    }

    const float2 rA = unpackf2(accA);
    const float2 rB = unpackf2(accB);
    const float4 r = make_float4(rA.x, rA.y, rB.x, rB.y);
    ((float4*)(out + n * DD))[lane]           = r;   // batch 0
    ((float4*)(out + NN * DD + n * DD))[lane] = r;   // batch 1 (broadcast)
}

// ---------------------------------------------------------------------------
extern "C" void kernel_launch(void* const* d_in, const int* in_sizes, int n_in,
                              void* d_out, int out_size) {
    const float* inputs = (const float*)d_in[0];   // (2, 10000, 128)
    const float* W      = (const float*)d_in[1];   // (128, 128)
    const float* W_attn = (const float*)d_in[2];   // (256, 1)
    const int*   edges  = (const int*)d_in[3];     // (330000, 2)
    float*       out    = (float*)d_out;           // (2, 10000, 128)

    cudaFuncSetAttribute(gemm_sd_kernel,
                         cudaFuncAttributeMaxDynamicSharedMemorySize, GEMM_SMEM);

    gemm_sd_kernel<<<GNBLK, GTPB, GEMM_SMEM>>>(inputs, W, W_attn);
    gat_agg_kernel<<<NN / 8, 256>>>(edges, out);
}

// round 7
// speedup vs baseline: 1.0600x; 1.0600x over previous
#include <cuda_runtime.h>
#include <cuda_fp16.h>

// Problem constants (fixed by the reference generator)
#define NN   10000          // nodes
#define BB   2              // batch
#define FF   128            // F_IN
#define DD   128            // D_EMB
#define EPN  33             // edges per node (DEG+1), contiguous per src node
#define ROWS (BB * NN)      // 20000 rows of X / h

// GEMM tiling: 80 rows/block -> 250 blocks, 2 resident/SM, single wave
#define GBM    80
#define GTPB   256
#define GNBLK  (ROWS / GBM)          // 250
#define XPITCH 136                   // halves per smem row (bank-staggered)
#define XS_BYTES  (GBM * XPITCH * 2)            // 21760
#define GEMM_SMEM (XS_BYTES + 2 * 8 * GBM * 4)  // + sd partials = 26880

// Scratch (device globals — no cudaMalloc allowed)
// Interleaved h: g_hx[node*32 + grp] = {b0 h2(4g,4g+1), b0 h2(4g+2,4g+3),
//                                       b1 h2(4g,4g+1), b1 h2(4g+2,4g+3)}
__device__ uint4 g_hx[NN * 32];     // 5.12 MB, both batches interleaved
__device__ float g_s[ROWS];         // h @ a_src (fp32)
__device__ float g_d[ROWS];         // h @ a_dst (fp32)

__device__ __forceinline__ unsigned packh2(float lo, float hi) {
    __half2 h = __floats2half2_rn(lo, hi);
    return *(unsigned*)&h;
}
__device__ __forceinline__ void ffma2(unsigned long long& acc,
                                      unsigned long long a,
                                      unsigned long long b) {
    asm("fma.rn.f32x2 %0, %1, %2, %0;" : "+l"(acc) : "l"(a), "l"(b));
}
__device__ __forceinline__ unsigned long long packf2(float lo, float hi) {
    unsigned long long v;
    asm("mov.b64 %0, {%1, %2};" : "=l"(v) : "f"(lo), "f"(hi));
    return v;
}
__device__ __forceinline__ float2 unpackf2(unsigned long long v) {
    float2 r;
    asm("mov.b64 {%0, %1}, %2;" : "=f"(r.x), "=f"(r.y) : "l"(v));
    return r;
}

extern __shared__ char smem_raw[];

// ---------------------------------------------------------------------------
// Kernel A: h = X @ W via mma.sync.m16n8k16 (fp16 in, fp32 acc).
// 256 threads = 8 warps; warp w owns cols [w*16, w*16+16) (2 n-tiles).
// Block owns 80 rows (5 m-tiles); 250 blocks -> 2 resident per SM.
// Even/odd-kt accumulator split halves the dependent-HMMA chain.
// ---------------------------------------------------------------------------
__global__ __launch_bounds__(GTPB)
void gemm_sd_kernel(const float* __restrict__ inputs,
                    const float* __restrict__ W,
                    const float* __restrict__ W_attn) {
    __half (*Xs)[XPITCH] = (__half(*)[XPITCH])smem_raw;
    float* sd_s = (float*)(smem_raw + XS_BYTES);   // [8][GBM]
    float* sd_d = sd_s + 8 * GBM;

    const int t    = threadIdx.x;
    const int lane = t & 31;
    const int w    = t >> 5;
    const int rb   = blockIdx.x * GBM;
    const int g    = lane >> 2;      // 0..7
    const int tg   = lane & 3;       // 0..3
    const int wcol = w * 16;

    // --- Stage X tile: fp32 global -> fp16 smem (coalesced, MLP=10) ---
#pragma unroll
    for (int i = 0; i < 10; ++i) {
        int idx = t + i * GTPB;
        int row = idx >> 5, c4 = idx & 31;
        float4 v = ((const float4*)inputs)[(rb + row) * 32 + c4];
        *(uint2*)&Xs[row][c4 * 4] =
            make_uint2(packh2(v.x, v.y), packh2(v.z, v.w));
    }

    // --- W fragments (col-major B frag for m16n8k16), register-resident ---
    unsigned bf[2][8][2];
#pragma unroll
    for (int nt = 0; nt < 2; ++nt) {
        const int c = wcol + nt * 8 + g;
#pragma unroll
        for (int kt = 0; kt < 8; ++kt) {
            const int k0 = kt * 16 + tg * 2;
            bf[nt][kt][0] = packh2(W[k0 * DD + c],       W[(k0 + 1) * DD + c]);
            bf[nt][kt][1] = packh2(W[(k0 + 8) * DD + c], W[(k0 + 9) * DD + c]);
        }
    }
    float as[2][2], ad[2][2];
#pragma unroll
    for (int nt = 0; nt < 2; ++nt) {
        const int c = wcol + nt * 8 + tg * 2;
        as[nt][0] = W_attn[c];       as[nt][1] = W_attn[c + 1];
        ad[nt][0] = W_attn[DD + c];  ad[nt][1] = W_attn[DD + c + 1];
    }
    __syncthreads();

    // --- Main loop over 5 m-tiles ---
#pragma unroll 1
    for (int mt = 0; mt < 5; ++mt) {
        float accE[2][4], accO[2][4];   // even-kt / odd-kt chains
#pragma unroll
        for (int nt = 0; nt < 2; ++nt)
#pragma unroll
            for (int i = 0; i < 4; ++i) { accE[nt][i] = 0.f; accO[nt][i] = 0.f; }

#pragma unroll
        for (int kp = 0; kp < 4; ++kp) {
#pragma unroll
            for (int half = 0; half < 2; ++half) {
                const int kt = kp * 2 + half;
                const int r0 = mt * 16 + g;
                const int c0 = kt * 16 + tg * 2;
                unsigned a0 = *(const unsigned*)&Xs[r0][c0];
                unsigned a1 = *(const unsigned*)&Xs[r0 + 8][c0];
                unsigned a2 = *(const unsigned*)&Xs[r0][c0 + 8];
                unsigned a3 = *(const unsigned*)&Xs[r0 + 8][c0 + 8];
                float (*acc)[4] = half ? accO : accE;
#pragma unroll
                for (int nt = 0; nt < 2; ++nt) {
                    asm volatile(
                        "mma.sync.aligned.m16n8k16.row.col.f32.f16.f16.f32 "
                        "{%0,%1,%2,%3}, {%4,%5,%6,%7}, {%8,%9}, {%0,%1,%2,%3};"
                        : "+f"(acc[nt][0]), "+f"(acc[nt][1]),
                          "+f"(acc[nt][2]), "+f"(acc[nt][3])
                        : "r"(a0), "r"(a1), "r"(a2), "r"(a3),
                          "r"(bf[nt][kt][0]), "r"(bf[nt][kt][1]));
                }
            }
        }

        float acc[2][4];
#pragma unroll
        for (int nt = 0; nt < 2; ++nt)
#pragma unroll
            for (int i = 0; i < 4; ++i) acc[nt][i] = accE[nt][i] + accO[nt][i];

        // --- Epilogue: interleaved fp16 h store + s/d partials ---
        const int row0 = rb + mt * 16 + g;      // and row0 + 8; all < ROWS
#pragma unroll
        for (int nt = 0; nt < 2; ++nt) {
            const int colbase = wcol + nt * 8 + tg * 2;
            const int grp  = colbase >> 2;
            const int slot = (colbase >> 1) & 1;
            unsigned p0 = packh2(acc[nt][0], acc[nt][1]);   // row0
            unsigned p1 = packh2(acc[nt][2], acc[nt][3]);   // row0+8
            {
                int b = row0 >= NN, node = row0 - b * NN;
                ((unsigned*)g_hx)[(node * 32 + grp) * 4 + b * 2 + slot] = p0;
            }
            {
                int r1 = row0 + 8;
                int b = r1 >= NN, node = r1 - b * NN;
                ((unsigned*)g_hx)[(node * 32 + grp) * 4 + b * 2 + slot] = p1;
            }
        }

        float ps0 = 0.f, pd0 = 0.f, ps1 = 0.f, pd1 = 0.f;
#pragma unroll
        for (int nt = 0; nt < 2; ++nt) {
            ps0 = fmaf(acc[nt][0], as[nt][0], fmaf(acc[nt][1], as[nt][1], ps0));
            pd0 = fmaf(acc[nt][0], ad[nt][0], fmaf(acc[nt][1], ad[nt][1], pd0));
            ps1 = fmaf(acc[nt][2], as[nt][0], fmaf(acc[nt][3], as[nt][1], ps1));
            pd1 = fmaf(acc[nt][2], ad[nt][0], fmaf(acc[nt][3], ad[nt][1], pd1));
        }
#pragma unroll
        for (int off = 1; off <= 2; off <<= 1) {
            ps0 += __shfl_xor_sync(0xFFFFFFFFu, ps0, off);
            pd0 += __shfl_xor_sync(0xFFFFFFFFu, pd0, off);
            ps1 += __shfl_xor_sync(0xFFFFFFFFu, ps1, off);
            pd1 += __shfl_xor_sync(0xFFFFFFFFu, pd1, off);
        }
        if (tg == 0) {
            sd_s[w * GBM + mt * 16 + g]     = ps0;
            sd_d[w * GBM + mt * 16 + g]     = pd0;
            sd_s[w * GBM + mt * 16 + g + 8] = ps1;
            sd_d[w * GBM + mt * 16 + g + 8] = pd1;
        }
    }
    __syncthreads();

    if (t < GBM) {
        float s = 0.f, d = 0.f;
#pragma unroll
        for (int i = 0; i < 8; ++i) {
            s += sd_s[i * GBM + t];
            d += sd_d[i * GBM + t];
        }
        g_s[rb + t] = s;
        g_d[rb + t] = d;
    }
}

// ---------------------------------------------------------------------------
// Kernel B: warp-per-node attention + aggregation (round-5 version verbatim;
// the occupancy clamp experiment of round 6 regressed — at the L2 wall,
// extra resident warps only add L1tex queue contention).
// ---------------------------------------------------------------------------
__global__ __launch_bounds__(256)
void gat_agg_kernel(const int* __restrict__ edges,
                    float* __restrict__ out) {
    __shared__ int    offs[8][EPN];
    __shared__ float4 wpr[8][EPN];

    const int t    = threadIdx.x;
    const int lane = t & 31;
    const int wi   = t >> 5;
    const int n    = blockIdx.x * 8 + wi;

    // --- Phase 1: scores ---
    const int2 e2  = __ldg(&((const int2*)edges)[n * EPN + lane]);
    const int dstv = e2.y;
    const float s0 = __ldg(&g_s[n]);
    const float s1 = __ldg(&g_s[NN + n]);

    float sc0 = s0 + __ldg(&g_d[dstv]);
    float sc1 = s1 + __ldg(&g_d[NN + dstv]);
    sc0 = (sc0 > 0.0f) ? sc0 : 0.2f * sc0;   // leaky_relu(0.2)
    sc1 = (sc1 > 0.0f) ? sc1 : 0.2f * sc1;
    const float w0v = expf(fminf(fmaxf(sc0, -2.0f), 2.0f));
    const float w1v = expf(fminf(fmaxf(sc1, -2.0f), 2.0f));

    // edge 32 (broadcast; computed redundantly by all lanes)
    const int d32 = __ldg(&edges[(n * EPN + 32) * 2 + 1]);
    float sx0 = s0 + __ldg(&g_d[d32]);
    float sx1 = s1 + __ldg(&g_d[NN + d32]);
    sx0 = (sx0 > 0.0f) ? sx0 : 0.2f * sx0;
    sx1 = (sx1 > 0.0f) ? sx1 : 0.2f * sx1;
    const float w032 = expf(fminf(fmaxf(sx0, -2.0f), 2.0f));
    const float w132 = expf(fminf(fmaxf(sx1, -2.0f), 2.0f));

    // denom over batch-0 scores (33 edges); fold 1/denom into weights
    float dn = w0v;
#pragma unroll
    for (int off = 16; off > 0; off >>= 1)
        dn += __shfl_xor_sync(0xFFFFFFFFu, dn, off);
    dn += w032;
    const float inv = 1.0f / dn;

    offs[wi][lane] = dstv * (int)sizeof(uint4) * 32;   // byte offset of h row
    {
        const float a = w0v * inv, b = w1v * inv;
        wpr[wi][lane] = make_float4(a, a, b, b);
    }
    if (lane == 0) {
        offs[wi][32] = d32 * (int)sizeof(uint4) * 32;
        const float a = w032 * inv, b = w132 * inv;
        wpr[wi][32] = make_float4(a, a, b, b);
    }
    __syncwarp();

    // --- Phase 2: gather, 4-edge batches ---
    const char* hbase = (const char*)g_hx + lane * 16;
    unsigned long long accA = 0ull, accB = 0ull;   // feats (0,1), (2,3)

#pragma unroll
    for (int eb = 0; eb < 32; eb += 4) {
        int    of[4];
        uint4  v[4];
        float4 wp[4];
#pragma unroll
        for (int k = 0; k < 4; ++k) of[k] = offs[wi][eb + k];
#pragma unroll
        for (int k = 0; k < 4; ++k) v[k] = *(const uint4*)(hbase + of[k]);
#pragma unroll
        for (int k = 0; k < 4; ++k) wp[k] = wpr[wi][eb + k];
#pragma unroll
        for (int k = 0; k < 4; ++k) {
            const unsigned long long c0p = packf2(wp[k].x, wp[k].y);
            const unsigned long long c1p = packf2(wp[k].z, wp[k].w);
            float2 f0a = __half22float2(*(__half2*)&v[k].x);
            float2 f0b = __half22float2(*(__half2*)&v[k].y);
            float2 f1a = __half22float2(*(__half2*)&v[k].z);
            float2 f1b = __half22float2(*(__half2*)&v[k].w);
            ffma2(accA, packf2(f0a.x, f0a.y), c0p);
            ffma2(accA, packf2(f1a.x, f1a.y), c1p);
            ffma2(accB, packf2(f0b.x, f0b.y), c0p);
            ffma2(accB, packf2(f1b.x, f1b.y), c1p);
        }
    }
    {   // edge 32
        const int of = offs[wi][32];
        const float4 wp = wpr[wi][32];
        const uint4 v = *(const uint4*)(hbase + of);
        const unsigned long long c0p = packf2(wp.x, wp.y);
        const unsigned long long c1p = packf2(wp.z, wp.w);
        float2 f0a = __half22float2(*(__half2*)&v.x);
        float2 f0b = __half22float2(*(__half2*)&v.y);
        float2 f1a = __half22float2(*(__half2*)&v.z);
        float2 f1b = __half22float2(*(__half2*)&v.w);
        ffma2(accA, packf2(f0a.x, f0a.y), c0p);
        ffma2(accA, packf2(f1a.x, f1a.y), c1p);
        ffma2(accB, packf2(f0b.x, f0b.y), c0p);
        ffma2(accB, packf2(f1b.x, f1b.y), c1p);
    }

    const float2 rA = unpackf2(accA);
    const float2 rB = unpackf2(accB);
    const float4 r = make_float4(rA.x, rA.y, rB.x, rB.y);
    ((float4*)(out + n * DD))[lane]           = r;   // batch 0
    ((float4*)(out + NN * DD + n * DD))[lane] = r;   // batch 1 (broadcast)
}

// ---------------------------------------------------------------------------
extern "C" void kernel_launch(void* const* d_in, const int* in_sizes, int n_in,
                              void* d_out, int out_size) {
    const float* inputs = (const float*)d_in[0];   // (2, 10000, 128)
    const float* W      = (const float*)d_in[1];   // (128, 128)
    const float* W_attn = (const float*)d_in[2];   // (256, 1)
    const int*   edges  = (const int*)d_in[3];     // (330000, 2)
    float*       out    = (float*)d_out;           // (2, 10000, 128)

    cudaFuncSetAttribute(gemm_sd_kernel,
                         cudaFuncAttributeMaxDynamicSharedMemorySize, GEMM_SMEM);

    gemm_sd_kernel<<<GNBLK, GTPB, GEMM_SMEM>>>(inputs, W, W_attn);
    gat_agg_kernel<<<NN / 8, 256>>>(edges, out);
}

// round 8
// speedup vs baseline: 1.0830x; 1.0217x over previous
#include <cuda_runtime.h>
#include <cuda_fp16.h>

// Problem constants (fixed by the reference generator)
#define NN   10000          // nodes
#define BB   2              // batch
#define FF   128            // F_IN
#define DD   128            // D_EMB
#define EPN  33             // edges per node (DEG+1), contiguous per src node
#define ROWS (BB * NN)      // 20000 rows of X / h

// GEMM tiling: 80 rows/block -> 250 blocks, 2 resident/SM, single wave
#define GBM    80
#define GTPB   256
#define GNBLK  (ROWS / GBM)          // 250
#define XPITCH 136                   // halves per smem row (17x16B chunks: odd -> ldmatrix conflict-free)
#define WPITCH 136
#define XS_BYTES  (GBM * XPITCH * 2)             // 21760
#define WS_BYTES  (128 * WPITCH * 2)             // 34816
#define SD_BYTES  (2 * 8 * GBM * 4)              // 5120
#define GEMM_SMEM (XS_BYTES + WS_BYTES + SD_BYTES)   // 61696

// Scratch (device globals — no cudaMalloc allowed)
// Interleaved h: g_hx[node*32 + grp] = {b0 h2(4g,4g+1), b0 h2(4g+2,4g+3),
//                                       b1 h2(4g,4g+1), b1 h2(4g+2,4g+3)}
__device__ uint4 g_hx[NN * 32];     // 5.12 MB, both batches interleaved
__device__ float g_s[ROWS];         // h @ a_src (fp32)
__device__ float g_d[ROWS];         // h @ a_dst (fp32)

__device__ __forceinline__ unsigned packh2(float lo, float hi) {
    __half2 h = __floats2half2_rn(lo, hi);
    return *(unsigned*)&h;
}
__device__ __forceinline__ void ffma2(unsigned long long& acc,
                                      unsigned long long a,
                                      unsigned long long b) {
    asm("fma.rn.f32x2 %0, %1, %2, %0;" : "+l"(acc) : "l"(a), "l"(b));
}
__device__ __forceinline__ unsigned long long packf2(float lo, float hi) {
    unsigned long long v;
    asm("mov.b64 %0, {%1, %2};" : "=l"(v) : "f"(lo), "f"(hi));
    return v;
}
__device__ __forceinline__ float2 unpackf2(unsigned long long v) {
    float2 r;
    asm("mov.b64 {%0, %1}, %2;" : "=f"(r.x), "=f"(r.y) : "l"(v));
    return r;
}
__device__ __forceinline__ unsigned smem_u32(const void* p) {
    return (unsigned)__cvta_generic_to_shared(p);
}
__device__ __forceinline__ void ldmx4(unsigned& r0, unsigned& r1,
                                      unsigned& r2, unsigned& r3, unsigned a) {
    asm volatile("ldmatrix.sync.aligned.m8n8.x4.shared.b16 {%0,%1,%2,%3}, [%4];"
                 : "=r"(r0), "=r"(r1), "=r"(r2), "=r"(r3) : "r"(a));
}
__device__ __forceinline__ void ldmx2t(unsigned& r0, unsigned& r1, unsigned a) {
    asm volatile("ldmatrix.sync.aligned.m8n8.x2.trans.shared.b16 {%0,%1}, [%2];"
                 : "=r"(r0), "=r"(r1) : "r"(a));
}

extern __shared__ char smem_raw[];

// ---------------------------------------------------------------------------
// Kernel A: h = X @ W via mma.sync.m16n8k16 (fp16 in, fp32 acc).
// 256 threads = 8 warps; warp w owns cols [w*16, w*16+16) (2 n-tiles).
// Block owns 80 rows (5 m-tiles). ALL fragment loads via ldmatrix:
//   A: ldmatrix.x4 (1 warp-inst per (mt,kt), was 4x LDS.32/thread)
//   B: W staged to smem half once, then ldmatrix.x2.trans (16 warp-inst,
//      was 64 scalar LDG per thread).
// ---------------------------------------------------------------------------
__global__ __launch_bounds__(GTPB)
void gemm_sd_kernel(const float* __restrict__ inputs,
                    const float* __restrict__ W,
                    const float* __restrict__ W_attn) {
    __half (*Xs)[XPITCH] = (__half(*)[XPITCH])smem_raw;
    __half (*Ws)[WPITCH] = (__half(*)[WPITCH])(smem_raw + XS_BYTES);
    float* sd_s = (float*)(smem_raw + XS_BYTES + WS_BYTES);   // [8][GBM]
    float* sd_d = sd_s + 8 * GBM;

    const int t    = threadIdx.x;
    const int lane = t & 31;
    const int w    = t >> 5;
    const int rb   = blockIdx.x * GBM;
    const int tg   = lane & 3;       // 0..3
    const int wcol = w * 16;

    // --- Stage X tile: fp32 global -> fp16 smem (coalesced) ---
#pragma unroll
    for (int i = 0; i < 10; ++i) {
        int idx = t + i * GTPB;
        int row = idx >> 5, c4 = idx & 31;
        float4 v = ((const float4*)inputs)[(rb + row) * 32 + c4];
        *(uint2*)&Xs[row][c4 * 4] =
            make_uint2(packh2(v.x, v.y), packh2(v.z, v.w));
    }
    // --- Stage W: fp32 global -> fp16 smem (coalesced, 128x128) ---
#pragma unroll
    for (int i = 0; i < 16; ++i) {
        int idx = t + i * GTPB;          // over 4096 float4
        int k = idx >> 5, c4 = idx & 31;
        float4 v = ((const float4*)W)[idx];
        *(uint2*)&Ws[k][c4 * 4] =
            make_uint2(packh2(v.x, v.y), packh2(v.z, v.w));
    }
    __syncthreads();

    // --- B fragments via ldmatrix.x2.trans (W is row-major [k][c]) ---
    unsigned bf[2][8][2];
    {
        const int l16 = lane & 15;
#pragma unroll
        for (int nt = 0; nt < 2; ++nt)
#pragma unroll
            for (int kt = 0; kt < 8; ++kt) {
                unsigned a = smem_u32(&Ws[kt * 16 + l16][wcol + nt * 8]);
                ldmx2t(bf[nt][kt][0], bf[nt][kt][1], a);
            }
    }
    float as[2][2], ad[2][2];
#pragma unroll
    for (int nt = 0; nt < 2; ++nt) {
        const int c = wcol + nt * 8 + tg * 2;
        as[nt][0] = W_attn[c];       as[nt][1] = W_attn[c + 1];
        ad[nt][0] = W_attn[DD + c];  ad[nt][1] = W_attn[DD + c + 1];
    }

    // A-frag ldmatrix lane address components (row/col within tile)
    const int arow = (lane & 7) + (lane & 8);        // 0..15
    const int acol = (lane >> 4) << 3;               // 0 or 8

    // --- Main loop over 5 m-tiles ---
#pragma unroll 1
    for (int mt = 0; mt < 5; ++mt) {
        float accE[2][4], accO[2][4];   // even/odd-kt chains
#pragma unroll
        for (int nt = 0; nt < 2; ++nt)
#pragma unroll
            for (int i = 0; i < 4; ++i) { accE[nt][i] = 0.f; accO[nt][i] = 0.f; }

#pragma unroll
        for (int kt = 0; kt < 8; ++kt) {
            unsigned a0, a1, a2, a3;
            unsigned addr = smem_u32(&Xs[mt * 16 + arow][kt * 16 + acol]);
            ldmx4(a0, a1, a2, a3, addr);
            float (*acc)[4] = (kt & 1) ? accO : accE;
#pragma unroll
            for (int nt = 0; nt < 2; ++nt) {
                asm volatile(
                    "mma.sync.aligned.m16n8k16.row.col.f32.f16.f16.f32 "
                    "{%0,%1,%2,%3}, {%4,%5,%6,%7}, {%8,%9}, {%0,%1,%2,%3};"
                    : "+f"(acc[nt][0]), "+f"(acc[nt][1]),
                      "+f"(acc[nt][2]), "+f"(acc[nt][3])
                    : "r"(a0), "r"(a1), "r"(a2), "r"(a3),
                      "r"(bf[nt][kt][0]), "r"(bf[nt][kt][1]));
            }
        }

        float acc[2][4];
#pragma unroll
        for (int nt = 0; nt < 2; ++nt)
#pragma unroll
            for (int i = 0; i < 4; ++i) acc[nt][i] = accE[nt][i] + accO[nt][i];

        // --- Epilogue: interleaved fp16 h store + s/d partials ---
        const int g = lane >> 2;
        const int row0 = rb + mt * 16 + g;      // and row0 + 8; all < ROWS
#pragma unroll
        for (int nt = 0; nt < 2; ++nt) {
            const int colbase = wcol + nt * 8 + tg * 2;
            const int grp  = colbase >> 2;
            const int slot = (colbase >> 1) & 1;
            unsigned p0 = packh2(acc[nt][0], acc[nt][1]);   // row0
            unsigned p1 = packh2(acc[nt][2], acc[nt][3]);   // row0+8
            {
                int b = row0 >= NN, node = row0 - b * NN;
                ((unsigned*)g_hx)[(node * 32 + grp) * 4 + b * 2 + slot] = p0;
            }
            {
                int r1 = row0 + 8;
                int b = r1 >= NN, node = r1 - b * NN;
                ((unsigned*)g_hx)[(node * 32 + grp) * 4 + b * 2 + slot] = p1;
            }
        }

        float ps0 = 0.f, pd0 = 0.f, ps1 = 0.f, pd1 = 0.f;
#pragma unroll
        for (int nt = 0; nt < 2; ++nt) {
            ps0 = fmaf(acc[nt][0], as[nt][0], fmaf(acc[nt][1], as[nt][1], ps0));
            pd0 = fmaf(acc[nt][0], ad[nt][0], fmaf(acc[nt][1], ad[nt][1], pd0));
            ps1 = fmaf(acc[nt][2], as[nt][0], fmaf(acc[nt][3], as[nt][1], ps1));
            pd1 = fmaf(acc[nt][2], ad[nt][0], fmaf(acc[nt][3], ad[nt][1], pd1));
        }
#pragma unroll
        for (int off = 1; off <= 2; off <<= 1) {
            ps0 += __shfl_xor_sync(0xFFFFFFFFu, ps0, off);
            pd0 += __shfl_xor_sync(0xFFFFFFFFu, pd0, off);
            ps1 += __shfl_xor_sync(0xFFFFFFFFu, ps1, off);
            pd1 += __shfl_xor_sync(0xFFFFFFFFu, pd1, off);
        }
        if (tg == 0) {
            sd_s[w * GBM + mt * 16 + g]     = ps0;
            sd_d[w * GBM + mt * 16 + g]     = pd0;
            sd_s[w * GBM + mt * 16 + g + 8] = ps1;
            sd_d[w * GBM + mt * 16 + g + 8] = pd1;
        }
    }
    __syncthreads();

    if (t < GBM) {
        float s = 0.f, d = 0.f;
#pragma unroll
        for (int i = 0; i < 8; ++i) {
            s += sd_s[i * GBM + t];
            d += sd_d[i * GBM + t];
        }
        g_s[rb + t] = s;
        g_d[rb + t] = d;
    }
}

// ---------------------------------------------------------------------------
// Kernel B: warp-per-node attention + aggregation (best config: no clamp,
// regs=34, ~60% occ — at the L2 wall, higher occupancy regressed).
// ---------------------------------------------------------------------------
__global__ __launch_bounds__(256)
void gat_agg_kernel(const int* __restrict__ edges,
                    float* __restrict__ out) {
    __shared__ int    offs[8][EPN];
    __shared__ float4 wpr[8][EPN];

    const int t    = threadIdx.x;
    const int lane = t & 31;
    const int wi   = t >> 5;
    const int n    = blockIdx.x * 8 + wi;

    // --- Phase 1: scores ---
    const int2 e2  = __ldg(&((const int2*)edges)[n * EPN + lane]);
    const int dstv = e2.y;
    const float s0 = __ldg(&g_s[n]);
    const float s1 = __ldg(&g_s[NN + n]);

    float sc0 = s0 + __ldg(&g_d[dstv]);
    float sc1 = s1 + __ldg(&g_d[NN + dstv]);
    sc0 = (sc0 > 0.0f) ? sc0 : 0.2f * sc0;   // leaky_relu(0.2)
    sc1 = (sc1 > 0.0f) ? sc1 : 0.2f * sc1;
    const float w0v = expf(fminf(fmaxf(sc0, -2.0f), 2.0f));
    const float w1v = expf(fminf(fmaxf(sc1, -2.0f), 2.0f));

    // edge 32 (broadcast; computed redundantly by all lanes)
    const int d32 = __ldg(&edges[(n * EPN + 32) * 2 + 1]);
    float sx0 = s0 + __ldg(&g_d[d32]);
    float sx1 = s1 + __ldg(&g_d[NN + d32]);
    sx0 = (sx0 > 0.0f) ? sx0 : 0.2f * sx0;
    sx1 = (sx1 > 0.0f) ? sx1 : 0.2f * sx1;
    const float w032 = expf(fminf(fmaxf(sx0, -2.0f), 2.0f));
    const float w132 = expf(fminf(fmaxf(sx1, -2.0f), 2.0f));

    // denom over batch-0 scores (33 edges); fold 1/denom into weights
    float dn = w0v;
#pragma unroll
    for (int off = 16; off > 0; off >>= 1)
        dn += __shfl_xor_sync(0xFFFFFFFFu, dn, off);
    dn += w032;
    const float inv = 1.0f / dn;

    offs[wi][lane] = dstv * (int)sizeof(uint4) * 32;   // byte offset of h row
    {
        const float a = w0v * inv, b = w1v * inv;
        wpr[wi][lane] = make_float4(a, a, b, b);
    }
    if (lane == 0) {
        offs[wi][32] = d32 * (int)sizeof(uint4) * 32;
        const float a = w032 * inv, b = w132 * inv;
        wpr[wi][32] = make_float4(a, a, b, b);
    }
    __syncwarp();

    // --- Phase 2: gather, 4-edge batches ---
    const char* hbase = (const char*)g_hx + lane * 16;
    unsigned long long accA = 0ull, accB = 0ull;   // feats (0,1), (2,3)

#pragma unroll
    for (int eb = 0; eb < 32; eb += 4) {
        int    of[4];
        uint4  v[4];
        float4 wp[4];
#pragma unroll
        for (int k = 0; k < 4; ++k) of[k] = offs[wi][eb + k];
#pragma unroll
        for (int k = 0; k < 4; ++k) v[k] = *(const uint4*)(hbase + of[k]);
#pragma unroll
        for (int k = 0; k < 4; ++k) wp[k] = wpr[wi][eb + k];
#pragma unroll
        for (int k = 0; k < 4; ++k) {
            const unsigned long long c0p = packf2(wp[k].x, wp[k].y);
            const unsigned long long c1p = packf2(wp[k].z, wp[k].w);
            float2 f0a = __half22float2(*(__half2*)&v[k].x);
            float2 f0b = __half22float2(*(__half2*)&v[k].y);
            float2 f1a = __half22float2(*(__half2*)&v[k].z);
            float2 f1b = __half22float2(*(__half2*)&v[k].w);
            ffma2(accA, packf2(f0a.x, f0a.y), c0p);
            ffma2(accA, packf2(f1a.x, f1a.y), c1p);
            ffma2(accB, packf2(f0b.x, f0b.y), c0p);
            ffma2(accB, packf2(f1b.x, f1b.y), c1p);
        }
    }
    {   // edge 32
        const int of = offs[wi][32];
        const float4 wp = wpr[wi][32];
        const uint4 v = *(const uint4*)(hbase + of);
        const unsigned long long c0p = packf2(wp.x, wp.y);
        const unsigned long long c1p = packf2(wp.z, wp.w);
        float2 f0a = __half22float2(*(__half2*)&v.x);
        float2 f0b = __half22float2(*(__half2*)&v.y);
        float2 f1a = __half22float2(*(__half2*)&v.z);
        float2 f1b = __half22float2(*(__half2*)&v.w);
        ffma2(accA, packf2(f0a.x, f0a.y), c0p);
        ffma2(accA, packf2(f1a.x, f1a.y), c1p);
        ffma2(accB, packf2(f0b.x, f0b.y), c0p);
        ffma2(accB, packf2(f1b.x, f1b.y), c1p);
    }

    const float2 rA = unpackf2(accA);
    const float2 rB = unpackf2(accB);
    const float4 r = make_float4(rA.x, rA.y, rB.x, rB.y);
    ((float4*)(out + n * DD))[lane]           = r;   // batch 0
    ((float4*)(out + NN * DD + n * DD))[lane] = r;   // batch 1 (broadcast)
}

// ---------------------------------------------------------------------------
extern "C" void kernel_launch(void* const* d_in, const int* in_sizes, int n_in,
                              void* d_out, int out_size) {
    const float* inputs = (const float*)d_in[0];   // (2, 10000, 128)
    const float* W      = (const float*)d_in[1];   // (128, 128)
    const float* W_attn = (const float*)d_in[2];   // (256, 1)
    const int*   edges  = (const int*)d_in[3];     // (330000, 2)
    float*       out    = (float*)d_out;           // (2, 10000, 128)

    cudaFuncSetAttribute(gemm_sd_kernel,
                         cudaFuncAttributeMaxDynamicSharedMemorySize, GEMM_SMEM);

    gemm_sd_kernel<<<GNBLK, GTPB, GEMM_SMEM>>>(inputs, W, W_attn);
    gat_agg_kernel<<<NN / 8, 256>>>(edges, out);
}